// round 9
// baseline (speedup 1.0000x reference)
#include <cuda_runtime.h>
#include <cuda_bf16.h>
#include <math.h>

// ---------------- problem constants ----------------
#define BATCH 4
#define NNODE 2048
#define NSEQ  (BATCH*NNODE)   // 8192
#define HDIM  64
#define FDIM  64
#define G3H   192
#define KNN   8
#define ODIM  32

// ---------------- scratch (__device__ globals, no allocation) ----------------
__device__ float g_xp[2][NSEQ][G3H];        // precomputed x @ Wih.T + bih for both GRUs
__device__ float g_h[2][NSEQ][HDIM];        // 0: gru_sim hidden seq, 1: gru hidden seq
__device__ float g_sim[BATCH][NNODE*NNODE]; // similarity matrices
__device__ float g_vals[NSEQ][KNN];
__device__ int   g_idx[NSEQ][KNN];
__device__ float g_deg[NSEQ];
__device__ float g_dinv[NSEQ];
__device__ float g_xw[NSEQ*HDIM];
__device__ float g_o1[NSEQ*HDIM];
__device__ float g_o2[NSEQ*HDIM];
__device__ float g_mu[HDIM];
__device__ float g_var[HDIM];
__device__ float g_wpe[ODIM*HDIM];
__device__ float g_be[ODIM];

// ---------------- f32x2 helpers (FFMA2 path, sm_103a) ----------------
__device__ __forceinline__ unsigned long long pk2(float x, float y) {
    unsigned long long r;
    asm("mov.b64 %0, {%1,%2};" : "=l"(r) : "f"(x), "f"(y));
    return r;
}
__device__ __forceinline__ void upk2(unsigned long long v, float &x, float &y) {
    asm("mov.b64 {%0,%1}, %2;" : "=f"(x), "=f"(y) : "l"(v));
}
__device__ __forceinline__ unsigned long long ffma2(unsigned long long a,
                                                    unsigned long long b,
                                                    unsigned long long c) {
    unsigned long long d;
    asm("fma.rn.f32x2 %0, %1, %2, %3;" : "=l"(d) : "l"(a), "l"(b), "l"(c));
    return d;
}
__device__ __forceinline__ unsigned long long fadd2(unsigned long long a,
                                                    unsigned long long b) {
    unsigned long long d;
    asm("add.rn.f32x2 %0, %1, %2;" : "=l"(d) : "l"(a), "l"(b));
    return d;
}

__device__ __forceinline__ float sigm(float x) {
    return 1.0f / (1.0f + __expf(-x));
}
__device__ __forceinline__ float tanh_f(float x) {
    float ax = fabsf(x);
    float e = __expf(-2.0f * ax);
    float r = (1.0f - e) / (1.0f + e);
    return copysignf(r, x);
}

// ---------------- stage 1: xp = seq @ Wih.T + bih (both GRUs) ----------------
// seq[s][f] = x_seq[b, 7, f, jn], s = b*2048 + jn
__global__ void __launch_bounds__(384) xp_kernel(const float* __restrict__ x,
                                                 const float* __restrict__ WihS,
                                                 const float* __restrict__ bihS,
                                                 const float* __restrict__ Wih,
                                                 const float* __restrict__ bih) {
    __shared__ float sq[16][64];
    const int tid = threadIdx.x;
    const int base = blockIdx.x * 16;
    for (int t = tid; t < 16 * 64; t += 384) {
        int f = t >> 4, r = t & 15;
        int s = base + r;
        int b = s >> 11, jn = s & 2047;
        sq[r][f] = x[((b * 8 + 7) * 64 + f) * 2048 + jn];
    }
    __syncthreads();
    const int which = (tid >= G3H) ? 1 : 0;
    const int j = which ? tid - G3H : tid;
    const float* W = which ? Wih : WihS;
    const float bz = which ? bih[j] : bihS[j];
    float wr[64];
#pragma unroll
    for (int f = 0; f < 64; f++) wr[f] = W[j * 64 + f];
    for (int r = 0; r < 16; r++) {
        float acc = bz;
#pragma unroll
        for (int f = 0; f < 64; f++) acc = fmaf(sq[r][f], wr[f], acc);
        g_xp[which][base + r][j] = acc;
    }
}

// ---------------- stage 2: sequential GRU scans (2 blocks, one per GRU) ----------------
__global__ void __launch_bounds__(192, 1) gru_kernel(const float* __restrict__ Whh0,
                                                     const float* __restrict__ bhh0,
                                                     const float* __restrict__ Whh1,
                                                     const float* __restrict__ bhh1) {
    const int g = blockIdx.x;
    const float* Whh = g ? Whh1 : Whh0;
    const float* bhh = g ? bhh1 : bhh0;
    const float* xp = &g_xp[g][0][0];
    float* hout = &g_h[g][0][0];
    const int j = threadIdx.x;  // 0..191, owns output hp[j]

    unsigned long long w[32];
    {
        const float2* wp = (const float2*)(Whh + j * 64);
#pragma unroll
        for (int k = 0; k < 32; k++) { float2 t = wp[k]; w[k] = pk2(t.x, t.y); }
    }
    const float bj = bhh[j];

    __shared__ __align__(16) float shh[64];
    __shared__ float shp[192];
    if (j < 64) shh[j] = 0.0f;

    float xr = 0.f, xz = 0.f, xn = 0.f;
    if (j < 64) {
        xr = xp[j]; xz = xp[64 + j]; xn = xp[128 + j];
    }
    __syncthreads();

    for (int s = 0; s < NSEQ; s++) {
        // prefetch next step's xt (hidden under the matvec + barrier)
        float nxr = 0.f, nxz = 0.f, nxn = 0.f;
        if (j < 64 && s + 1 < NSEQ) {
            const float* p = xp + (s + 1) * G3H;
            nxr = __ldg(p + j); nxz = __ldg(p + 64 + j); nxn = __ldg(p + 128 + j);
        }
        // hp[j] = bhh[j] + dot(h, Whh[j,:])  via f32x2
        unsigned long long a0 = 0ull, a1 = 0ull, a2 = 0ull, a3 = 0ull;
#pragma unroll
        for (int k = 0; k < 16; k += 2) {
            float4 q0 = *(const float4*)(shh + 4 * k);
            float4 q1 = *(const float4*)(shh + 4 * k + 4);
            a0 = ffma2(w[2 * k],     pk2(q0.x, q0.y), a0);
            a1 = ffma2(w[2 * k + 1], pk2(q0.z, q0.w), a1);
            a2 = ffma2(w[2 * k + 2], pk2(q1.x, q1.y), a2);
            a3 = ffma2(w[2 * k + 3], pk2(q1.z, q1.w), a3);
        }
        unsigned long long t01 = fadd2(a0, a1);
        unsigned long long t23 = fadd2(a2, a3);
        unsigned long long tt = fadd2(t01, t23);
        float fx, fy; upk2(tt, fx, fy);
        shp[j] = bj + fx + fy;
        __syncthreads();

        if (j < 64) {
            float hpr = shp[j], hpz = shp[64 + j], hpn = shp[128 + j];
            float r = sigm(xr + hpr);
            float z = sigm(xz + hpz);
            float ng = tanh_f(xn + r * hpn);
            float hn = (1.0f - z) * ng + z * shh[j];
            shh[j] = hn;
            hout[s * 64 + j] = hn;
            xr = nxr; xz = nxz; xn = nxn;
        }
        __syncthreads();
    }
}

// ---------------- stage 3: sim[b] = H H^T (per batch), 64x64 tiles ----------------
__global__ void __launch_bounds__(256) sim_kernel() {
    const int b = blockIdx.z, bi = blockIdx.y, bj = blockIdx.x;
    __shared__ float A[64][65];
    __shared__ float B[64][65];
    const int tid = threadIdx.x;
    const float* H = &g_h[0][(size_t)b * NNODE][0];
    for (int t = tid; t < 4096; t += 256) {
        int r = t >> 6, c = t & 63;
        A[r][c] = H[(bi * 64 + r) * 64 + c];
        B[r][c] = H[(bj * 64 + r) * 64 + c];
    }
    __syncthreads();
    const int ty = tid >> 4, tx = tid & 15;
    float acc[4][4];
#pragma unroll
    for (int u = 0; u < 4; u++)
#pragma unroll
        for (int v = 0; v < 4; v++) acc[u][v] = 0.f;
    for (int k = 0; k < 64; k++) {
        float a[4], bb[4];
#pragma unroll
        for (int u = 0; u < 4; u++) a[u] = A[ty * 4 + u][k];
#pragma unroll
        for (int v = 0; v < 4; v++) bb[v] = B[tx * 4 + v][k];
#pragma unroll
        for (int u = 0; u < 4; u++)
#pragma unroll
            for (int v = 0; v < 4; v++) acc[u][v] = fmaf(a[u], bb[v], acc[u][v]);
    }
    float* C = &g_sim[b][0];
#pragma unroll
    for (int u = 0; u < 4; u++)
#pragma unroll
        for (int v = 0; v < 4; v++)
            C[(size_t)(bi * 64 + ty * 4 + u) * NNODE + (bj * 64 + tx * 4 + v)] = acc[u][v];
}

// ---------------- stage 4: per-row top-8 (one warp per row) ----------------
__global__ void __launch_bounds__(128) topk_kernel() {
    const int warp = threadIdx.x >> 5, lane = threadIdx.x & 31;
    const int row = blockIdx.x * 4 + warp;  // 0..8191
    const int b = row >> 11, i = row & 2047;
    const float* S = &g_sim[b][(size_t)i * NNODE];

    float v8[8]; int i8[8];
#pragma unroll
    for (int t = 0; t < 8; t++) { v8[t] = -3.402823e38f; i8[t] = -1; }

    for (int jj = lane; jj < NNODE; jj += 32) {
        if (jj == i) continue;
        float v = S[jj];
        if (v > v8[7]) {
            v8[7] = v; i8[7] = jj;
#pragma unroll
            for (int q = 7; q > 0; q--) {
                if (v8[q] > v8[q - 1]) {
                    float tv = v8[q - 1]; v8[q - 1] = v8[q]; v8[q] = tv;
                    int ti = i8[q - 1]; i8[q - 1] = i8[q]; i8[q] = ti;
                }
            }
        }
    }
    // warp merge: 8 rounds of argmax over each lane's current head
    const unsigned FULL = 0xffffffffu;
    for (int t = 0; t < KNN; t++) {
        float bv = v8[0]; int bi2 = i8[0]; int bl = lane;
#pragma unroll
        for (int off = 16; off > 0; off >>= 1) {
            float ov = __shfl_down_sync(FULL, bv, off);
            int oi = __shfl_down_sync(FULL, bi2, off);
            int ol = __shfl_down_sync(FULL, bl, off);
            if (ov > bv || (ov == bv && oi < bi2)) { bv = ov; bi2 = oi; bl = ol; }
        }
        bv = __shfl_sync(FULL, bv, 0);
        bi2 = __shfl_sync(FULL, bi2, 0);
        bl = __shfl_sync(FULL, bl, 0);
        if (lane == bl) {
#pragma unroll
            for (int q = 0; q < 7; q++) { v8[q] = v8[q + 1]; i8[q] = i8[q + 1]; }
            v8[7] = -3.402823e38f; i8[7] = -1;
        }
        if (lane == 0) { g_vals[row][t] = bv; g_idx[row][t] = bi2; }
    }
}

// ---------------- stage 5: degree + dinv ----------------
__global__ void deg_init_kernel() {
    int t = blockIdx.x * 256 + threadIdx.x;
    if (t < NSEQ) g_deg[t] = 1.0f;  // self loop weight
}
__global__ void deg_scatter_kernel() {
    int t = blockIdx.x * 256 + threadIdx.x;
    if (t < NSEQ * KNN) {
        int s = t >> 3, k = t & 7;
        int b = s >> 11;
        atomicAdd(&g_deg[(b << 11) + g_idx[s][k]], g_vals[s][k]);
    }
}
__global__ void dinv_kernel() {
    int t = blockIdx.x * 256 + threadIdx.x;
    if (t < NSEQ) {
        float di = rsqrtf(g_deg[t]);
        if (isinf(di)) di = 0.0f;
        g_dinv[t] = di;
    }
}

// ---------------- stage 6: xw = act(X) @ W.T ----------------
__global__ void __launch_bounds__(256) xw_kernel(const float* __restrict__ W,
                                                 int src, int relu) {
    __shared__ float sx[4][64];
    __shared__ float wT[64][64];
    const int tid = threadIdx.x;
    const float* X = src ? g_o1 : &g_h[1][0][0];
    for (int t = tid; t < 4096; t += 256) {
        int jj = t >> 6, f = t & 63;
        wT[f][jj] = W[jj * 64 + f];
    }
    const int s0 = blockIdx.x * 4;
    {
        int r = tid >> 6, f = tid & 63;
        float v = X[(s0 + r) * 64 + f];
        if (relu) v = fmaxf(v, 0.0f);
        sx[r][f] = v;
    }
    __syncthreads();
    const int r = tid >> 6, j = tid & 63;
    float acc = 0.f;
#pragma unroll
    for (int f = 0; f < 64; f++) acc = fmaf(sx[r][f], wT[f][j], acc);
    g_xw[(s0 + r) * 64 + j] = acc;
}

// ---------------- stage 7: GCN init (bias + self loop) + scatter ----------------
__global__ void init_out_kernel(int layer, const float* __restrict__ bias) {
    int t = blockIdx.x * 256 + threadIdx.x;  // < 524288
    int s = t >> 6, j = t & 63;
    float di = g_dinv[s];
    float* O = layer ? g_o2 : g_o1;
    O[t] = bias[j] + di * di * g_xw[t];
}
__global__ void scatter_kernel(int layer) {
    int t = blockIdx.x * 256 + threadIdx.x;  // < 4194304
    int e = t >> 6, c = t & 63;
    int s = e >> 3, k = e & 7;
    int b = s >> 11;
    int dst = (b << 11) + g_idx[s][k];
    float norm = g_dinv[s] * g_vals[s][k] * g_dinv[dst];
    float* O = layer ? g_o2 : g_o1;
    atomicAdd(&O[dst * 64 + c], norm * g_xw[s * 64 + c]);
}

// ---------------- stage 8: BN stats over relu(o2) ----------------
__global__ void __launch_bounds__(256) stats_kernel() {
    const int c = blockIdx.x;
    float s = 0.f, q = 0.f;
    for (int r = threadIdx.x; r < NSEQ; r += 256) {
        float v = fmaxf(g_o2[r * 64 + c], 0.0f);
        s += v;
        q = fmaf(v, v, q);
    }
    __shared__ float ss[256], sq2[256];
    ss[threadIdx.x] = s; sq2[threadIdx.x] = q;
    __syncthreads();
    for (int o = 128; o > 0; o >>= 1) {
        if (threadIdx.x < o) {
            ss[threadIdx.x] += ss[threadIdx.x + o];
            sq2[threadIdx.x] += sq2[threadIdx.x + o];
        }
        __syncthreads();
    }
    if (threadIdx.x == 0) {
        float mu = ss[0] / (float)NSEQ;
        g_mu[c] = mu;
        g_var[c] = sq2[0] / (float)NSEQ - mu * mu;
    }
}

// ---------------- stage 9: fold BN into predictor: Wp' = Wp*a, b' = bp + (beta - mu*a) @ Wp.T
__global__ void __launch_bounds__(64) prep_kernel(const float* __restrict__ gamma,
                                                  const float* __restrict__ beta,
                                                  const float* __restrict__ Wp,
                                                  const float* __restrict__ bp) {
    __shared__ float sa[64], sm[64];
    const int c = threadIdx.x;
    float a = gamma[c] * rsqrtf(g_var[c] + 1e-5f);
    sa[c] = a;
    sm[c] = beta[c] - g_mu[c] * a;
    __syncthreads();
    for (int t = c; t < ODIM * 64; t += 64) {
        int o = t >> 6, cc = t & 63;
        g_wpe[o * 64 + cc] = Wp[o * 64 + cc] * sa[cc];
    }
    if (c < ODIM) {
        float acc = bp[c];
#pragma unroll
        for (int cc = 0; cc < 64; cc++) acc = fmaf(sm[cc], Wp[c * 64 + cc], acc);
        g_be[c] = acc;
    }
}

// ---------------- stage 10: out = relu(o2) @ Wp'.T + b' ----------------
__global__ void __launch_bounds__(256) final_kernel(float* __restrict__ out) {
    __shared__ float sx[8][64];
    __shared__ float wT[64][32];
    __shared__ float sb[32];
    const int tid = threadIdx.x;
    const int s0 = blockIdx.x * 8;
    for (int t = tid; t < ODIM * 64; t += 256) {
        int o = t >> 6, cc = t & 63;
        wT[cc][o] = g_wpe[o * 64 + cc];
    }
    for (int t = tid; t < 512; t += 256) {
        int r = t >> 6, cc = t & 63;
        sx[r][cc] = fmaxf(g_o2[(s0 + r) * 64 + cc], 0.0f);
    }
    if (tid < ODIM) sb[tid] = g_be[tid];
    __syncthreads();
    const int r = tid >> 5, o = tid & 31;
    float acc = sb[o];
#pragma unroll
    for (int cc = 0; cc < 64; cc++) acc = fmaf(sx[r][cc], wT[cc][o], acc);
    out[(s0 + r) * ODIM + o] = acc;
}

// ---------------- launch ----------------
extern "C" void kernel_launch(void* const* d_in, const int* in_sizes, int n_in,
                              void* d_out, int out_size) {
    const float* x     = (const float*)d_in[0];   // [4,8,64,2048]
    const float* WihS  = (const float*)d_in[1];
    const float* WhhS  = (const float*)d_in[2];
    const float* bihS  = (const float*)d_in[3];
    const float* bhhS  = (const float*)d_in[4];
    const float* Wih   = (const float*)d_in[5];
    const float* Whh   = (const float*)d_in[6];
    const float* bih   = (const float*)d_in[7];
    const float* bhh   = (const float*)d_in[8];
    const float* W1    = (const float*)d_in[9];
    const float* b1    = (const float*)d_in[10];
    const float* W2    = (const float*)d_in[11];
    const float* b2    = (const float*)d_in[12];
    const float* gamma = (const float*)d_in[13];
    const float* beta  = (const float*)d_in[14];
    const float* Wp    = (const float*)d_in[15];
    const float* bp    = (const float*)d_in[16];
    float* out = (float*)d_out;

    xp_kernel<<<NSEQ / 16, 384>>>(x, WihS, bihS, Wih, bih);
    gru_kernel<<<2, 192>>>(WhhS, bhhS, Whh, bhh);
    sim_kernel<<<dim3(32, 32, 4), 256>>>();
    topk_kernel<<<NSEQ / 4, 128>>>();
    deg_init_kernel<<<NSEQ / 256, 256>>>();
    deg_scatter_kernel<<<NSEQ * KNN / 256, 256>>>();
    dinv_kernel<<<NSEQ / 256, 256>>>();

    // GCN layer 1: input h_out (no relu)
    xw_kernel<<<NSEQ / 4, 256>>>(W1, 0, 0);
    init_out_kernel<<<NSEQ * 64 / 256, 256>>>(0, b1);
    scatter_kernel<<<NSEQ * KNN * 64 / 256, 256>>>(0);

    // GCN layer 2: input relu(o1)
    xw_kernel<<<NSEQ / 4, 256>>>(W2, 1, 1);
    init_out_kernel<<<NSEQ * 64 / 256, 256>>>(1, b2);
    scatter_kernel<<<NSEQ * KNN * 64 / 256, 256>>>(1);

    // BN + predictor
    stats_kernel<<<64, 256>>>();
    prep_kernel<<<1, 64>>>(gamma, beta, Wp, bp);
    final_kernel<<<NSEQ / 8, 256>>>(out);
}

// round 10
// speedup vs baseline: 1.2394x; 1.2394x over previous
#include <cuda_runtime.h>
#include <cuda_bf16.h>
#include <math.h>

// ---------------- problem constants ----------------
#define BATCH 4
#define NNODE 2048
#define NSEQ  (BATCH*NNODE)   // 8192
#define HDIM  64
#define FDIM  64
#define G3H   192
#define KNN   8
#define ODIM  32

// ---------------- scratch (__device__ globals, no allocation) ----------------
__device__ float g_xp[2][NSEQ][G3H];        // precomputed x @ Wih.T + bih for both GRUs
__device__ float g_h[2][NSEQ][HDIM];        // 0: gru_sim hidden seq, 1: gru hidden seq
__device__ float g_sim[BATCH][NNODE*NNODE]; // similarity matrices
__device__ float g_vals[NSEQ][KNN];
__device__ int   g_idx[NSEQ][KNN];
__device__ float g_deg[NSEQ];
__device__ float g_dinv[NSEQ];
__device__ float g_xw[NSEQ*HDIM];
__device__ float g_o1[NSEQ*HDIM];
__device__ float g_o2[NSEQ*HDIM];
__device__ float g_mu[HDIM];
__device__ float g_var[HDIM];
__device__ float g_wpe[ODIM*HDIM];
__device__ float g_be[ODIM];

// ---------------- f32x2 helpers (FFMA2 path, sm_103a) ----------------
__device__ __forceinline__ unsigned long long pk2(float x, float y) {
    unsigned long long r;
    asm("mov.b64 %0, {%1,%2};" : "=l"(r) : "f"(x), "f"(y));
    return r;
}
__device__ __forceinline__ void upk2(unsigned long long v, float &x, float &y) {
    asm("mov.b64 {%0,%1}, %2;" : "=f"(x), "=f"(y) : "l"(v));
}
__device__ __forceinline__ unsigned long long ffma2(unsigned long long a,
                                                    unsigned long long b,
                                                    unsigned long long c) {
    unsigned long long d;
    asm("fma.rn.f32x2 %0, %1, %2, %3;" : "=l"(d) : "l"(a), "l"(b), "l"(c));
    return d;
}
__device__ __forceinline__ unsigned long long fadd2(unsigned long long a,
                                                    unsigned long long b) {
    unsigned long long d;
    asm("add.rn.f32x2 %0, %1, %2;" : "=l"(d) : "l"(a), "l"(b));
    return d;
}
__device__ __forceinline__ float hsum2(unsigned long long v) {
    float x, y; upk2(v, x, y); return x + y;
}

__device__ __forceinline__ float sigm(float x) {
    return 1.0f / (1.0f + __expf(-x));
}
__device__ __forceinline__ float tanh_f(float x) {
    float ax = fabsf(x);
    float e = __expf(-2.0f * ax);
    float r = (1.0f - e) / (1.0f + e);
    return copysignf(r, x);
}

// ---------------- stage 1: xp = seq @ Wih.T + bih (both GRUs) ----------------
// seq[s][f] = x_seq[b, 7, f, jn], s = b*2048 + jn
__global__ void __launch_bounds__(384) xp_kernel(const float* __restrict__ x,
                                                 const float* __restrict__ WihS,
                                                 const float* __restrict__ bihS,
                                                 const float* __restrict__ Wih,
                                                 const float* __restrict__ bih) {
    __shared__ float sq[16][64];
    const int tid = threadIdx.x;
    const int base = blockIdx.x * 16;
    for (int t = tid; t < 16 * 64; t += 384) {
        int f = t >> 4, r = t & 15;
        int s = base + r;
        int b = s >> 11, jn = s & 2047;
        sq[r][f] = x[((b * 8 + 7) * 64 + f) * 2048 + jn];
    }
    __syncthreads();
    const int which = (tid >= G3H) ? 1 : 0;
    const int j = which ? tid - G3H : tid;
    const float* W = which ? Wih : WihS;
    const float bz = which ? bih[j] : bihS[j];
    float wr[64];
#pragma unroll
    for (int f = 0; f < 64; f++) wr[f] = W[j * 64 + f];
    for (int r = 0; r < 16; r++) {
        float acc = bz;
#pragma unroll
        for (int f = 0; f < 64; f++) acc = fmaf(sq[r][f], wr[f], acc);
        g_xp[which][base + r][j] = acc;
    }
}

// ---------------- stage 2: sequential GRU scans (2 blocks, one per GRU) ----------------
// 128 threads: thread (j, half) computes the r/z/n partial dots over 32 h
// elements; halves merged with one shfl_xor; gates computed redundantly by
// both halves (fully thread-local). Double-buffered h -> ONE barrier/step.
__global__ void __launch_bounds__(128, 1) gru_kernel(const float* __restrict__ Whh0,
                                                     const float* __restrict__ bhh0,
                                                     const float* __restrict__ Whh1,
                                                     const float* __restrict__ bhh1) {
    const int g = blockIdx.x;
    const float* Whh = g ? Whh1 : Whh0;
    const float* bhh = g ? bhh1 : bhh0;
    const float* xp = &g_xp[g][0][0];
    float* hout = &g_h[g][0][0];

    const int tid = threadIdx.x;
    const int j = tid >> 1;      // 0..63
    const int half = tid & 1;    // which 32-element half of h
    const int hoff = half * 32;

    // weight rows for gates r,z,n (this thread's half), packed f32x2
    unsigned long long wr[16], wz[16], wn[16];
    {
        const float2* pr = (const float2*)(Whh + (size_t)j * 64 + hoff);
        const float2* pz = (const float2*)(Whh + (size_t)(64 + j) * 64 + hoff);
        const float2* pn = (const float2*)(Whh + (size_t)(128 + j) * 64 + hoff);
#pragma unroll
        for (int k = 0; k < 16; k++) {
            float2 a = pr[k]; wr[k] = pk2(a.x, a.y);
            float2 b = pz[k]; wz[k] = pk2(b.x, b.y);
            float2 c = pn[k]; wn[k] = pk2(c.x, c.y);
        }
    }
    const float br = bhh[j], bz2 = bhh[64 + j], bn = bhh[128 + j];

    __shared__ __align__(16) float shh[2][64];
    if (tid < 64) shh[0][tid] = 0.0f;

    float xr = xp[j], xz = xp[64 + j], xn = xp[128 + j];
    __syncthreads();

    int p = 0;
    const unsigned FULL = 0xffffffffu;
    for (int s = 0; s < NSEQ; s++) {
        // prefetch next step's xt (hidden under the matvec)
        float nxr = 0.f, nxz = 0.f, nxn = 0.f;
        if (s + 1 < NSEQ) {
            const float* q = xp + (size_t)(s + 1) * G3H;
            nxr = __ldg(q + j); nxz = __ldg(q + 64 + j); nxn = __ldg(q + 128 + j);
        }

        float hj = shh[p][j];
        const ulonglong2* hp2 = (const ulonglong2*)(&shh[p][hoff]);
        unsigned long long ar0 = 0ull, ar1 = 0ull;
        unsigned long long az0 = 0ull, az1 = 0ull;
        unsigned long long an0 = 0ull, an1 = 0ull;
#pragma unroll
        for (int k = 0; k < 8; k++) {
            ulonglong2 h2 = hp2[k];
            ar0 = ffma2(wr[2 * k],     h2.x, ar0);
            ar1 = ffma2(wr[2 * k + 1], h2.y, ar1);
            az0 = ffma2(wz[2 * k],     h2.x, az0);
            az1 = ffma2(wz[2 * k + 1], h2.y, az1);
            an0 = ffma2(wn[2 * k],     h2.x, an0);
            an1 = ffma2(wn[2 * k + 1], h2.y, an1);
        }
        float sr = hsum2(fadd2(ar0, ar1));
        float sz = hsum2(fadd2(az0, az1));
        float sn = hsum2(fadd2(an0, an1));
        sr += __shfl_xor_sync(FULL, sr, 1);
        sz += __shfl_xor_sync(FULL, sz, 1);
        sn += __shfl_xor_sync(FULL, sn, 1);

        float r = sigm(xr + br + sr);
        float z = sigm(xz + bz2 + sz);
        float ng = tanh_f(xn + r * (bn + sn));
        float hn = fmaf(z, hj - ng, ng);   // (1-z)*ng + z*h

        int np = p ^ 1;
        if (half == 0) {
            shh[np][j] = hn;
            hout[(size_t)s * 64 + j] = hn;
        }
        xr = nxr; xz = nxz; xn = nxn;
        p = np;
        __syncthreads();
    }
}

// ---------------- stage 3: sim[b] = H H^T (per batch), 64x64 tiles ----------------
__global__ void __launch_bounds__(256) sim_kernel() {
    const int b = blockIdx.z, bi = blockIdx.y, bj = blockIdx.x;
    __shared__ float A[64][65];
    __shared__ float B[64][65];
    const int tid = threadIdx.x;
    const float* H = &g_h[0][(size_t)b * NNODE][0];
    for (int t = tid; t < 4096; t += 256) {
        int r = t >> 6, c = t & 63;
        A[r][c] = H[(bi * 64 + r) * 64 + c];
        B[r][c] = H[(bj * 64 + r) * 64 + c];
    }
    __syncthreads();
    const int ty = tid >> 4, tx = tid & 15;
    float acc[4][4];
#pragma unroll
    for (int u = 0; u < 4; u++)
#pragma unroll
        for (int v = 0; v < 4; v++) acc[u][v] = 0.f;
    for (int k = 0; k < 64; k++) {
        float a[4], bb[4];
#pragma unroll
        for (int u = 0; u < 4; u++) a[u] = A[ty * 4 + u][k];
#pragma unroll
        for (int v = 0; v < 4; v++) bb[v] = B[tx * 4 + v][k];
#pragma unroll
        for (int u = 0; u < 4; u++)
#pragma unroll
            for (int v = 0; v < 4; v++) acc[u][v] = fmaf(a[u], bb[v], acc[u][v]);
    }
    float* C = &g_sim[b][0];
#pragma unroll
    for (int u = 0; u < 4; u++)
#pragma unroll
        for (int v = 0; v < 4; v++)
            C[(size_t)(bi * 64 + ty * 4 + u) * NNODE + (bj * 64 + tx * 4 + v)] = acc[u][v];
}

// ---------------- stage 4: per-row top-8 (one warp per row, float4 stream) ----------------
__device__ __forceinline__ void tk_insert(float v, int jj, float* v8, int* i8) {
    if (v > v8[7]) {
        v8[7] = v; i8[7] = jj;
#pragma unroll
        for (int q = 7; q > 0; q--) {
            if (v8[q] > v8[q - 1]) {
                float tv = v8[q - 1]; v8[q - 1] = v8[q]; v8[q] = tv;
                int ti = i8[q - 1]; i8[q - 1] = i8[q]; i8[q] = ti;
            }
        }
    }
}

__global__ void __launch_bounds__(128) topk_kernel() {
    const int warp = threadIdx.x >> 5, lane = threadIdx.x & 31;
    const int row = blockIdx.x * 4 + warp;  // 0..8191
    const int b = row >> 11, i = row & 2047;
    const float4* S4 = (const float4*)&g_sim[b][(size_t)i * NNODE];

    float v8[8]; int i8[8];
#pragma unroll
    for (int t = 0; t < 8; t++) { v8[t] = -3.402823e38f; i8[t] = -1; }

#pragma unroll 2
    for (int q = lane; q < NNODE / 4; q += 32) {
        float4 v = S4[q];
        int jj = q * 4;
        if (jj != i)     tk_insert(v.x, jj,     v8, i8);
        if (jj + 1 != i) tk_insert(v.y, jj + 1, v8, i8);
        if (jj + 2 != i) tk_insert(v.z, jj + 2, v8, i8);
        if (jj + 3 != i) tk_insert(v.w, jj + 3, v8, i8);
    }

    // warp merge: 8 rounds of argmax over each lane's current head
    const unsigned FULL = 0xffffffffu;
    for (int t = 0; t < KNN; t++) {
        float bv = v8[0]; int bi2 = i8[0]; int bl = lane;
#pragma unroll
        for (int off = 16; off > 0; off >>= 1) {
            float ov = __shfl_down_sync(FULL, bv, off);
            int oi = __shfl_down_sync(FULL, bi2, off);
            int ol = __shfl_down_sync(FULL, bl, off);
            if (ov > bv || (ov == bv && oi < bi2)) { bv = ov; bi2 = oi; bl = ol; }
        }
        bv = __shfl_sync(FULL, bv, 0);
        bi2 = __shfl_sync(FULL, bi2, 0);
        bl = __shfl_sync(FULL, bl, 0);
        if (lane == bl) {
#pragma unroll
            for (int q = 0; q < 7; q++) { v8[q] = v8[q + 1]; i8[q] = i8[q + 1]; }
            v8[7] = -3.402823e38f; i8[7] = -1;
        }
        if (lane == 0) { g_vals[row][t] = bv; g_idx[row][t] = bi2; }
    }
}

// ---------------- stage 5: degree + dinv ----------------
__global__ void deg_init_kernel() {
    int t = blockIdx.x * 256 + threadIdx.x;
    if (t < NSEQ) g_deg[t] = 1.0f;  // self loop weight
}
__global__ void deg_scatter_kernel() {
    int t = blockIdx.x * 256 + threadIdx.x;
    if (t < NSEQ * KNN) {
        int s = t >> 3, k = t & 7;
        int b = s >> 11;
        atomicAdd(&g_deg[(b << 11) + g_idx[s][k]], g_vals[s][k]);
    }
}
__global__ void dinv_kernel() {
    int t = blockIdx.x * 256 + threadIdx.x;
    if (t < NSEQ) {
        float di = rsqrtf(g_deg[t]);
        if (isinf(di)) di = 0.0f;
        g_dinv[t] = di;
    }
}

// ---------------- stage 6: xw = act(X) @ W.T ----------------
__global__ void __launch_bounds__(256) xw_kernel(const float* __restrict__ W,
                                                 int src, int relu) {
    __shared__ float sx[4][64];
    __shared__ float wT[64][64];
    const int tid = threadIdx.x;
    const float* X = src ? g_o1 : &g_h[1][0][0];
    for (int t = tid; t < 4096; t += 256) {
        int jj = t >> 6, f = t & 63;
        wT[f][jj] = W[jj * 64 + f];
    }
    const int s0 = blockIdx.x * 4;
    {
        int r = tid >> 6, f = tid & 63;
        float v = X[(s0 + r) * 64 + f];
        if (relu) v = fmaxf(v, 0.0f);
        sx[r][f] = v;
    }
    __syncthreads();
    const int r = tid >> 6, j = tid & 63;
    float acc = 0.f;
#pragma unroll
    for (int f = 0; f < 64; f++) acc = fmaf(sx[r][f], wT[f][j], acc);
    g_xw[(s0 + r) * 64 + j] = acc;
}

// ---------------- stage 7: GCN init (bias + self loop) + scatter ----------------
__global__ void init_out_kernel(int layer, const float* __restrict__ bias) {
    int t = blockIdx.x * 256 + threadIdx.x;  // < 524288
    int s = t >> 6, j = t & 63;
    float di = g_dinv[s];
    float* O = layer ? g_o2 : g_o1;
    O[t] = bias[j] + di * di * g_xw[t];
}
__global__ void scatter_kernel(int layer) {
    int t = blockIdx.x * 256 + threadIdx.x;  // < 4194304
    int e = t >> 6, c = t & 63;
    int s = e >> 3, k = e & 7;
    int b = s >> 11;
    int dst = (b << 11) + g_idx[s][k];
    float norm = g_dinv[s] * g_vals[s][k] * g_dinv[dst];
    float* O = layer ? g_o2 : g_o1;
    atomicAdd(&O[dst * 64 + c], norm * g_xw[s * 64 + c]);
}

// ---------------- stage 8: BN stats over relu(o2) ----------------
__global__ void __launch_bounds__(256) stats_kernel() {
    const int c = blockIdx.x;
    float s = 0.f, q = 0.f;
    for (int r = threadIdx.x; r < NSEQ; r += 256) {
        float v = fmaxf(g_o2[r * 64 + c], 0.0f);
        s += v;
        q = fmaf(v, v, q);
    }
    __shared__ float ss[256], sq2[256];
    ss[threadIdx.x] = s; sq2[threadIdx.x] = q;
    __syncthreads();
    for (int o = 128; o > 0; o >>= 1) {
        if (threadIdx.x < o) {
            ss[threadIdx.x] += ss[threadIdx.x + o];
            sq2[threadIdx.x] += sq2[threadIdx.x + o];
        }
        __syncthreads();
    }
    if (threadIdx.x == 0) {
        float mu = ss[0] / (float)NSEQ;
        g_mu[c] = mu;
        g_var[c] = sq2[0] / (float)NSEQ - mu * mu;
    }
}

// ---------------- stage 9: fold BN into predictor ----------------
__global__ void __launch_bounds__(64) prep_kernel(const float* __restrict__ gamma,
                                                  const float* __restrict__ beta,
                                                  const float* __restrict__ Wp,
                                                  const float* __restrict__ bp) {
    __shared__ float sa[64], sm[64];
    const int c = threadIdx.x;
    float a = gamma[c] * rsqrtf(g_var[c] + 1e-5f);
    sa[c] = a;
    sm[c] = beta[c] - g_mu[c] * a;
    __syncthreads();
    for (int t = c; t < ODIM * 64; t += 64) {
        int o = t >> 6, cc = t & 63;
        g_wpe[o * 64 + cc] = Wp[o * 64 + cc] * sa[cc];
    }
    if (c < ODIM) {
        float acc = bp[c];
#pragma unroll
        for (int cc = 0; cc < 64; cc++) acc = fmaf(sm[cc], Wp[c * 64 + cc], acc);
        g_be[c] = acc;
    }
}

// ---------------- stage 10: out = relu(o2) @ Wp'.T + b' ----------------
__global__ void __launch_bounds__(256) final_kernel(float* __restrict__ out) {
    __shared__ float sx[8][64];
    __shared__ float wT[64][32];
    __shared__ float sb[32];
    const int tid = threadIdx.x;
    const int s0 = blockIdx.x * 8;
    for (int t = tid; t < ODIM * 64; t += 256) {
        int o = t >> 6, cc = t & 63;
        wT[cc][o] = g_wpe[o * 64 + cc];
    }
    for (int t = tid; t < 512; t += 256) {
        int r = t >> 6, cc = t & 63;
        sx[r][cc] = fmaxf(g_o2[(s0 + r) * 64 + cc], 0.0f);
    }
    if (tid < ODIM) sb[tid] = g_be[tid];
    __syncthreads();
    const int r = tid >> 5, o = tid & 31;
    float acc = sb[o];
#pragma unroll
    for (int cc = 0; cc < 64; cc++) acc = fmaf(sx[r][cc], wT[cc][o], acc);
    out[(s0 + r) * ODIM + o] = acc;
}

// ---------------- launch ----------------
extern "C" void kernel_launch(void* const* d_in, const int* in_sizes, int n_in,
                              void* d_out, int out_size) {
    const float* x     = (const float*)d_in[0];   // [4,8,64,2048]
    const float* WihS  = (const float*)d_in[1];
    const float* WhhS  = (const float*)d_in[2];
    const float* bihS  = (const float*)d_in[3];
    const float* bhhS  = (const float*)d_in[4];
    const float* Wih   = (const float*)d_in[5];
    const float* Whh   = (const float*)d_in[6];
    const float* bih   = (const float*)d_in[7];
    const float* bhh   = (const float*)d_in[8];
    const float* W1    = (const float*)d_in[9];
    const float* b1    = (const float*)d_in[10];
    const float* W2    = (const float*)d_in[11];
    const float* b2    = (const float*)d_in[12];
    const float* gamma = (const float*)d_in[13];
    const float* beta  = (const float*)d_in[14];
    const float* Wp    = (const float*)d_in[15];
    const float* bp    = (const float*)d_in[16];
    float* out = (float*)d_out;

    xp_kernel<<<NSEQ / 16, 384>>>(x, WihS, bihS, Wih, bih);
    gru_kernel<<<2, 128>>>(WhhS, bhhS, Whh, bhh);
    sim_kernel<<<dim3(32, 32, 4), 256>>>();
    topk_kernel<<<NSEQ / 4, 128>>>();
    deg_init_kernel<<<NSEQ / 256, 256>>>();
    deg_scatter_kernel<<<NSEQ * KNN / 256, 256>>>();
    dinv_kernel<<<NSEQ / 256, 256>>>();

    // GCN layer 1: input h_out (no relu)
    xw_kernel<<<NSEQ / 4, 256>>>(W1, 0, 0);
    init_out_kernel<<<NSEQ * 64 / 256, 256>>>(0, b1);
    scatter_kernel<<<NSEQ * KNN * 64 / 256, 256>>>(0);

    // GCN layer 2: input relu(o1)
    xw_kernel<<<NSEQ / 4, 256>>>(W2, 1, 1);
    init_out_kernel<<<NSEQ * 64 / 256, 256>>>(1, b2);
    scatter_kernel<<<NSEQ * KNN * 64 / 256, 256>>>(1);

    // BN + predictor
    stats_kernel<<<64, 256>>>();
    prep_kernel<<<1, 64>>>(gamma, beta, Wp, bp);
    final_kernel<<<NSEQ / 8, 256>>>(out);
}

// round 12
// speedup vs baseline: 1.2671x; 1.0224x over previous
#include <cuda_runtime.h>
#include <cuda_bf16.h>
#include <math.h>

// ---------------- problem constants ----------------
#define BATCH 4
#define NNODE 2048
#define NSEQ  (BATCH*NNODE)   // 8192
#define HDIM  64
#define FDIM  64
#define G3H   192
#define KNN   8
#define ODIM  32

// ---------------- scratch (__device__ globals, no allocation) ----------------
__device__ float g_xp[2][NSEQ][G3H];        // precomputed x @ Wih.T + bih for both GRUs
__device__ float g_h[2][NSEQ][HDIM];        // 0: gru_sim hidden seq, 1: gru hidden seq
__device__ float g_sim[BATCH][NNODE*NNODE]; // similarity matrices
__device__ float g_vals[NSEQ][KNN];
__device__ int   g_idx[NSEQ][KNN];
__device__ float g_deg[NSEQ];
__device__ float g_dinv[NSEQ];
__device__ float g_xw[NSEQ*HDIM];
__device__ float g_o1[NSEQ*HDIM];
__device__ float g_o2[NSEQ*HDIM];
__device__ float g_mu[HDIM];
__device__ float g_var[HDIM];
__device__ float g_wpe[ODIM*HDIM];
__device__ float g_be[ODIM];

// ---------------- f32x2 helpers (FFMA2 path, sm_103a) ----------------
__device__ __forceinline__ unsigned long long pk2(float x, float y) {
    unsigned long long r;
    asm("mov.b64 %0, {%1,%2};" : "=l"(r) : "f"(x), "f"(y));
    return r;
}
__device__ __forceinline__ void upk2(unsigned long long v, float &x, float &y) {
    asm("mov.b64 {%0,%1}, %2;" : "=f"(x), "=f"(y) : "l"(v));
}
__device__ __forceinline__ unsigned long long ffma2(unsigned long long a,
                                                    unsigned long long b,
                                                    unsigned long long c) {
    unsigned long long d;
    asm("fma.rn.f32x2 %0, %1, %2, %3;" : "=l"(d) : "l"(a), "l"(b), "l"(c));
    return d;
}
__device__ __forceinline__ unsigned long long fadd2(unsigned long long a,
                                                    unsigned long long b) {
    unsigned long long d;
    asm("add.rn.f32x2 %0, %1, %2;" : "=l"(d) : "l"(a), "l"(b));
    return d;
}
__device__ __forceinline__ float hsum2(unsigned long long v) {
    float x, y; upk2(v, x, y); return x + y;
}

// fast gates: MUFU-only (no div.rn subroutine on the critical chain)
__device__ __forceinline__ float sigm(float x) {
    return __fdividef(1.0f, 1.0f + __expf(-x));
}
__device__ __forceinline__ float tanh_f(float x) {
    float ax = fabsf(x);
    float e = __expf(-2.0f * ax);
    float r = (1.0f - e) * __fdividef(1.0f, 1.0f + e);
    return copysignf(r, x);
}

// ---------------- stage 1: xp = seq @ Wih.T + bih (both GRUs) ----------------
// seq[s][f] = x_seq[b, 7, f, jn], s = b*2048 + jn
__global__ void __launch_bounds__(384) xp_kernel(const float* __restrict__ x,
                                                 const float* __restrict__ WihS,
                                                 const float* __restrict__ bihS,
                                                 const float* __restrict__ Wih,
                                                 const float* __restrict__ bih) {
    __shared__ float sq[16][64];
    const int tid = threadIdx.x;
    const int base = blockIdx.x * 16;
    for (int t = tid; t < 16 * 64; t += 384) {
        int f = t >> 4, r = t & 15;
        int s = base + r;
        int b = s >> 11, jn = s & 2047;
        sq[r][f] = x[((b * 8 + 7) * 64 + f) * 2048 + jn];
    }
    __syncthreads();
    const int which = (tid >= G3H) ? 1 : 0;
    const int j = which ? tid - G3H : tid;
    const float* W = which ? Wih : WihS;
    const float bz = which ? bih[j] : bihS[j];
    float wr[64];
#pragma unroll
    for (int f = 0; f < 64; f++) wr[f] = W[j * 64 + f];
    for (int r = 0; r < 16; r++) {
        float acc = bz;
#pragma unroll
        for (int f = 0; f < 64; f++) acc = fmaf(sq[r][f], wr[f], acc);
        g_xp[which][base + r][j] = acc;
    }
}

// ---------------- stage 2: sequential GRU scans (2 blocks, one per GRU) ----------------
// 256 threads: thread (j, q) computes r/z/n partial dots over a 16-elem
// quarter of h; merged with shfl_xor(1) + shfl_xor(2); gates redundant across
// the 4 threads of each j. 2-deep xp prefetch. Double-buffered h, ONE barrier.
__global__ void __launch_bounds__(256, 1) gru_kernel(const float* __restrict__ Whh0,
                                                     const float* __restrict__ bhh0,
                                                     const float* __restrict__ Whh1,
                                                     const float* __restrict__ bhh1) {
    const int g = blockIdx.x;
    const float* Whh = g ? Whh1 : Whh0;
    const float* bhh = g ? bhh1 : bhh0;
    const float* xp = &g_xp[g][0][0];
    float* hout = &g_h[g][0][0];

    const int tid = threadIdx.x;
    const int j = tid >> 2;      // 0..63
    const int q = tid & 3;       // quarter of h
    const int hoff = q * 16;

    // weight quarters for gates r,z,n, packed f32x2 (8 each)
    unsigned long long wr[8], wz[8], wn[8];
    {
        const float2* pr = (const float2*)(Whh + (size_t)j * 64 + hoff);
        const float2* pz = (const float2*)(Whh + (size_t)(64 + j) * 64 + hoff);
        const float2* pn = (const float2*)(Whh + (size_t)(128 + j) * 64 + hoff);
#pragma unroll
        for (int k = 0; k < 8; k++) {
            float2 a = pr[k]; wr[k] = pk2(a.x, a.y);
            float2 b = pz[k]; wz[k] = pk2(b.x, b.y);
            float2 c = pn[k]; wn[k] = pk2(c.x, c.y);
        }
    }
    const float br = bhh[j], bz2 = bhh[64 + j], bn = bhh[128 + j];

    __shared__ __align__(16) float shh[2][64];
    if (tid < 64) shh[0][tid] = 0.0f;

    // 2-deep xp prefetch pipeline
    float xr0 = xp[j],        xz0 = xp[64 + j],        xn0 = xp[128 + j];
    float xr1 = xp[G3H + j],  xz1 = xp[G3H + 64 + j],  xn1 = xp[G3H + 128 + j];
    __syncthreads();

    int p = 0;
    const unsigned FULL = 0xffffffffu;
    for (int s = 0; s < NSEQ; s++) {
        // prefetch xt for s+2 (consumed ~2 steps from now)
        float xr2 = 0.f, xz2 = 0.f, xn2 = 0.f;
        if (s + 2 < NSEQ) {
            const float* pq = xp + (size_t)(s + 2) * G3H;
            xr2 = __ldg(pq + j); xz2 = __ldg(pq + 64 + j); xn2 = __ldg(pq + 128 + j);
        }

        float hj = shh[p][j];
        const ulonglong2* hp2 = (const ulonglong2*)(&shh[p][hoff]);
        ulonglong2 h0 = hp2[0];
        ulonglong2 h1 = hp2[1];
        unsigned long long ar0, ar1, az0, az1, an0, an1;
        ar0 = ffma2(wr[0], h0.x, 0ull); ar1 = ffma2(wr[1], h0.y, 0ull);
        az0 = ffma2(wz[0], h0.x, 0ull); az1 = ffma2(wz[1], h0.y, 0ull);
        an0 = ffma2(wn[0], h0.x, 0ull); an1 = ffma2(wn[1], h0.y, 0ull);
        ar0 = ffma2(wr[2], h1.x, ar0);  ar1 = ffma2(wr[3], h1.y, ar1);
        az0 = ffma2(wz[2], h1.x, az0);  az1 = ffma2(wz[3], h1.y, az1);
        an0 = ffma2(wn[2], h1.x, an0);  an1 = ffma2(wn[3], h1.y, an1);
        ulonglong2 h2 = hp2[2];
        ulonglong2 h3 = hp2[3];
        ar0 = ffma2(wr[4], h2.x, ar0);  ar1 = ffma2(wr[5], h2.y, ar1);
        az0 = ffma2(wz[4], h2.x, az0);  az1 = ffma2(wz[5], h2.y, az1);
        an0 = ffma2(wn[4], h2.x, an0);  an1 = ffma2(wn[5], h2.y, an1);
        ar0 = ffma2(wr[6], h3.x, ar0);  ar1 = ffma2(wr[7], h3.y, ar1);
        az0 = ffma2(wz[6], h3.x, az0);  az1 = ffma2(wz[7], h3.y, az1);
        an0 = ffma2(wn[6], h3.x, an0);  an1 = ffma2(wn[7], h3.y, an1);

        float sr = hsum2(fadd2(ar0, ar1));
        float sz = hsum2(fadd2(az0, az1));
        float sn = hsum2(fadd2(an0, an1));
        sr += __shfl_xor_sync(FULL, sr, 1);
        sz += __shfl_xor_sync(FULL, sz, 1);
        sn += __shfl_xor_sync(FULL, sn, 1);
        sr += __shfl_xor_sync(FULL, sr, 2);
        sz += __shfl_xor_sync(FULL, sz, 2);
        sn += __shfl_xor_sync(FULL, sn, 2);

        float r = sigm(xr0 + br + sr);
        float z = sigm(xz0 + bz2 + sz);
        float ng = tanh_f(xn0 + r * (bn + sn));
        float hn = fmaf(z, hj - ng, ng);   // (1-z)*ng + z*h

        int np = p ^ 1;
        if (q == 0) {
            shh[np][j] = hn;
            hout[(size_t)s * 64 + j] = hn;
        }
        xr0 = xr1; xz0 = xz1; xn0 = xn1;
        xr1 = xr2; xz1 = xz2; xn1 = xn2;
        p = np;
        __syncthreads();
    }
}

// ---------------- stage 3: sim[b] = H H^T (per batch), 64x64 tiles ----------------
__global__ void __launch_bounds__(256) sim_kernel() {
    const int b = blockIdx.z, bi = blockIdx.y, bj = blockIdx.x;
    __shared__ float A[64][65];
    __shared__ float B[64][65];
    const int tid = threadIdx.x;
    const float* H = &g_h[0][(size_t)b * NNODE][0];
    for (int t = tid; t < 4096; t += 256) {
        int r = t >> 6, c = t & 63;
        A[r][c] = H[(bi * 64 + r) * 64 + c];
        B[r][c] = H[(bj * 64 + r) * 64 + c];
    }
    __syncthreads();
    const int ty = tid >> 4, tx = tid & 15;
    float acc[4][4];
#pragma unroll
    for (int u = 0; u < 4; u++)
#pragma unroll
        for (int v = 0; v < 4; v++) acc[u][v] = 0.f;
    for (int k = 0; k < 64; k++) {
        float a[4], bb[4];
#pragma unroll
        for (int u = 0; u < 4; u++) a[u] = A[ty * 4 + u][k];
#pragma unroll
        for (int v = 0; v < 4; v++) bb[v] = B[tx * 4 + v][k];
#pragma unroll
        for (int u = 0; u < 4; u++)
#pragma unroll
            for (int v = 0; v < 4; v++) acc[u][v] = fmaf(a[u], bb[v], acc[u][v]);
    }
    float* C = &g_sim[b][0];
#pragma unroll
    for (int u = 0; u < 4; u++)
#pragma unroll
        for (int v = 0; v < 4; v++)
            C[(size_t)(bi * 64 + ty * 4 + u) * NNODE + (bj * 64 + tx * 4 + v)] = acc[u][v];
}

// ---------------- stage 4: per-row top-8 (one warp per row, float4 stream) ----------------
__device__ __forceinline__ void tk_insert(float v, int jj, float* v8, int* i8) {
    if (v > v8[7]) {
        v8[7] = v; i8[7] = jj;
#pragma unroll
        for (int q = 7; q > 0; q--) {
            if (v8[q] > v8[q - 1]) {
                float tv = v8[q - 1]; v8[q - 1] = v8[q]; v8[q] = tv;
                int ti = i8[q - 1]; i8[q - 1] = i8[q]; i8[q] = ti;
            }
        }
    }
}

__global__ void __launch_bounds__(128) topk_kernel() {
    const int warp = threadIdx.x >> 5, lane = threadIdx.x & 31;
    const int row = blockIdx.x * 4 + warp;  // 0..8191
    const int b = row >> 11, i = row & 2047;
    const float4* S4 = (const float4*)&g_sim[b][(size_t)i * NNODE];

    float v8[8]; int i8[8];
#pragma unroll
    for (int t = 0; t < 8; t++) { v8[t] = -3.402823e38f; i8[t] = -1; }

#pragma unroll 2
    for (int q = lane; q < NNODE / 4; q += 32) {
        float4 v = S4[q];
        int jj = q * 4;
        if (jj != i)     tk_insert(v.x, jj,     v8, i8);
        if (jj + 1 != i) tk_insert(v.y, jj + 1, v8, i8);
        if (jj + 2 != i) tk_insert(v.z, jj + 2, v8, i8);
        if (jj + 3 != i) tk_insert(v.w, jj + 3, v8, i8);
    }

    // warp merge: 8 rounds of argmax over each lane's current head
    const unsigned FULL = 0xffffffffu;
    for (int t = 0; t < KNN; t++) {
        float bv = v8[0]; int bi2 = i8[0]; int bl = lane;
#pragma unroll
        for (int off = 16; off > 0; off >>= 1) {
            float ov = __shfl_down_sync(FULL, bv, off);
            int oi = __shfl_down_sync(FULL, bi2, off);
            int ol = __shfl_down_sync(FULL, bl, off);
            if (ov > bv || (ov == bv && oi < bi2)) { bv = ov; bi2 = oi; bl = ol; }
        }
        bv = __shfl_sync(FULL, bv, 0);
        bi2 = __shfl_sync(FULL, bi2, 0);
        bl = __shfl_sync(FULL, bl, 0);
        if (lane == bl) {
#pragma unroll
            for (int q = 0; q < 7; q++) { v8[q] = v8[q + 1]; i8[q] = i8[q + 1]; }
            v8[7] = -3.402823e38f; i8[7] = -1;
        }
        if (lane == 0) { g_vals[row][t] = bv; g_idx[row][t] = bi2; }
    }
}

// ---------------- stage 5: degree + dinv ----------------
__global__ void deg_init_kernel() {
    int t = blockIdx.x * 256 + threadIdx.x;
    if (t < NSEQ) g_deg[t] = 1.0f;  // self loop weight
}
__global__ void deg_scatter_kernel() {
    int t = blockIdx.x * 256 + threadIdx.x;
    if (t < NSEQ * KNN) {
        int s = t >> 3, k = t & 7;
        int b = s >> 11;
        atomicAdd(&g_deg[(b << 11) + g_idx[s][k]], g_vals[s][k]);
    }
}
__global__ void dinv_kernel() {
    int t = blockIdx.x * 256 + threadIdx.x;
    if (t < NSEQ) {
        float di = rsqrtf(g_deg[t]);
        if (isinf(di)) di = 0.0f;
        g_dinv[t] = di;
    }
}

// ---------------- stage 6: xw = act(X) @ W.T ----------------
__global__ void __launch_bounds__(256) xw_kernel(const float* __restrict__ W,
                                                 int src, int relu) {
    __shared__ float sx[4][64];
    __shared__ float wT[64][64];
    const int tid = threadIdx.x;
    const float* X = src ? g_o1 : &g_h[1][0][0];
    for (int t = tid; t < 4096; t += 256) {
        int jj = t >> 6, f = t & 63;
        wT[f][jj] = W[jj * 64 + f];
    }
    const int s0 = blockIdx.x * 4;
    {
        int r = tid >> 6, f = tid & 63;
        float v = X[(s0 + r) * 64 + f];
        if (relu) v = fmaxf(v, 0.0f);
        sx[r][f] = v;
    }
    __syncthreads();
    const int r = tid >> 6, j = tid & 63;
    float acc = 0.f;
#pragma unroll
    for (int f = 0; f < 64; f++) acc = fmaf(sx[r][f], wT[f][j], acc);
    g_xw[(s0 + r) * 64 + j] = acc;
}

// ---------------- stage 7: GCN init (bias + self loop) + scatter ----------------
__global__ void init_out_kernel(int layer, const float* __restrict__ bias) {
    int t = blockIdx.x * 256 + threadIdx.x;  // < 524288
    int s = t >> 6, j = t & 63;
    float di = g_dinv[s];
    float* O = layer ? g_o2 : g_o1;
    O[t] = bias[j] + di * di * g_xw[t];
}
__global__ void scatter_kernel(int layer) {
    int t = blockIdx.x * 256 + threadIdx.x;  // < 4194304
    int e = t >> 6, c = t & 63;
    int s = e >> 3, k = e & 7;
    int b = s >> 11;
    int dst = (b << 11) + g_idx[s][k];
    float norm = g_dinv[s] * g_vals[s][k] * g_dinv[dst];
    float* O = layer ? g_o2 : g_o1;
    atomicAdd(&O[dst * 64 + c], norm * g_xw[s * 64 + c]);
}

// ---------------- stage 8: BN stats over relu(o2) ----------------
__global__ void __launch_bounds__(256) stats_kernel() {
    const int c = blockIdx.x;
    float s = 0.f, q = 0.f;
    for (int r = threadIdx.x; r < NSEQ; r += 256) {
        float v = fmaxf(g_o2[r * 64 + c], 0.0f);
        s += v;
        q = fmaf(v, v, q);
    }
    __shared__ float ss[256], sq2[256];
    ss[threadIdx.x] = s; sq2[threadIdx.x] = q;
    __syncthreads();
    for (int o = 128; o > 0; o >>= 1) {
        if (threadIdx.x < o) {
            ss[threadIdx.x] += ss[threadIdx.x + o];
            sq2[threadIdx.x] += sq2[threadIdx.x + o];
        }
        __syncthreads();
    }
    if (threadIdx.x == 0) {
        float mu = ss[0] / (float)NSEQ;
        g_mu[c] = mu;
        g_var[c] = sq2[0] / (float)NSEQ - mu * mu;
    }
}

// ---------------- stage 9: fold BN into predictor ----------------
__global__ void __launch_bounds__(64) prep_kernel(const float* __restrict__ gamma,
                                                  const float* __restrict__ beta,
                                                  const float* __restrict__ Wp,
                                                  const float* __restrict__ bp) {
    __shared__ float sa[64], sm[64];
    const int c = threadIdx.x;
    float a = gamma[c] * rsqrtf(g_var[c] + 1e-5f);
    sa[c] = a;
    sm[c] = beta[c] - g_mu[c] * a;
    __syncthreads();
    for (int t = c; t < ODIM * 64; t += 64) {
        int o = t >> 6, cc = t & 63;
        g_wpe[o * 64 + cc] = Wp[o * 64 + cc] * sa[cc];
    }
    if (c < ODIM) {
        float acc = bp[c];
#pragma unroll
        for (int cc = 0; cc < 64; cc++) acc = fmaf(sm[cc], Wp[c * 64 + cc], acc);
        g_be[c] = acc;
    }
}

// ---------------- stage 10: out = relu(o2) @ Wp'.T + b' ----------------
__global__ void __launch_bounds__(256) final_kernel(float* __restrict__ out) {
    __shared__ float sx[8][64];
    __shared__ float wT[64][32];
    __shared__ float sb[32];
    const int tid = threadIdx.x;
    const int s0 = blockIdx.x * 8;
    for (int t = tid; t < ODIM * 64; t += 256) {
        int o = t >> 6, cc = t & 63;
        wT[cc][o] = g_wpe[o * 64 + cc];
    }
    for (int t = tid; t < 512; t += 256) {
        int r = t >> 6, cc = t & 63;
        sx[r][cc] = fmaxf(g_o2[(s0 + r) * 64 + cc], 0.0f);
    }
    if (tid < ODIM) sb[tid] = g_be[tid];
    __syncthreads();
    const int r = tid >> 5, o = tid & 31;
    float acc = sb[o];
#pragma unroll
    for (int cc = 0; cc < 64; cc++) acc = fmaf(sx[r][cc], wT[cc][o], acc);
    out[(s0 + r) * ODIM + o] = acc;
}

// ---------------- launch ----------------
extern "C" void kernel_launch(void* const* d_in, const int* in_sizes, int n_in,
                              void* d_out, int out_size) {
    const float* x     = (const float*)d_in[0];   // [4,8,64,2048]
    const float* WihS  = (const float*)d_in[1];
    const float* WhhS  = (const float*)d_in[2];
    const float* bihS  = (const float*)d_in[3];
    const float* bhhS  = (const float*)d_in[4];
    const float* Wih   = (const float*)d_in[5];
    const float* Whh   = (const float*)d_in[6];
    const float* bih   = (const float*)d_in[7];
    const float* bhh   = (const float*)d_in[8];
    const float* W1    = (const float*)d_in[9];
    const float* b1    = (const float*)d_in[10];
    const float* W2    = (const float*)d_in[11];
    const float* b2    = (const float*)d_in[12];
    const float* gamma = (const float*)d_in[13];
    const float* beta  = (const float*)d_in[14];
    const float* Wp    = (const float*)d_in[15];
    const float* bp    = (const float*)d_in[16];
    float* out = (float*)d_out;

    xp_kernel<<<NSEQ / 16, 384>>>(x, WihS, bihS, Wih, bih);
    gru_kernel<<<2, 256>>>(WhhS, bhhS, Whh, bhh);
    sim_kernel<<<dim3(32, 32, 4), 256>>>();
    topk_kernel<<<NSEQ / 4, 128>>>();
    deg_init_kernel<<<NSEQ / 256, 256>>>();
    deg_scatter_kernel<<<NSEQ * KNN / 256, 256>>>();
    dinv_kernel<<<NSEQ / 256, 256>>>();

    // GCN layer 1: input h_out (no relu)
    xw_kernel<<<NSEQ / 4, 256>>>(W1, 0, 0);
    init_out_kernel<<<NSEQ * 64 / 256, 256>>>(0, b1);
    scatter_kernel<<<NSEQ * KNN * 64 / 256, 256>>>(0);

    // GCN layer 2: input relu(o1)
    xw_kernel<<<NSEQ / 4, 256>>>(W2, 1, 1);
    init_out_kernel<<<NSEQ * 64 / 256, 256>>>(1, b2);
    scatter_kernel<<<NSEQ * KNN * 64 / 256, 256>>>(1);

    // BN + predictor
    stats_kernel<<<64, 256>>>();
    prep_kernel<<<1, 64>>>(gamma, beta, Wp, bp);
    final_kernel<<<NSEQ / 8, 256>>>(out);
}

// round 15
// speedup vs baseline: 1.6163x; 1.2756x over previous
#include <cuda_runtime.h>
#include <cuda_bf16.h>
#include <math.h>

// ---------------- problem constants ----------------
#define BATCH 4
#define NNODE 2048
#define NSEQ  (BATCH*NNODE)   // 8192
#define HDIM  64
#define FDIM  64
#define G3H   192
#define KNN   8
#define ODIM  32

// ---------------- scratch (__device__ globals, no allocation) ----------------
// g_xp padded by 2 rows so the GRU prefetch needs no bounds check.
__device__ float g_xp[2][NSEQ + 2][G3H];    // PRE-SCALED xt (log2 domain, see xp_kernel)
__device__ float g_h[2][NSEQ][HDIM];        // 0: gru_sim hidden seq, 1: gru hidden seq
__device__ float g_sim[BATCH][NNODE*NNODE]; // similarity matrices
__device__ float g_vals[NSEQ][KNN];
__device__ int   g_idx[NSEQ][KNN];
__device__ float g_deg[NSEQ];
__device__ float g_dinv[NSEQ];
__device__ float g_xw[NSEQ*HDIM];
__device__ float g_o1[NSEQ*HDIM];
__device__ float g_o2[NSEQ*HDIM];
__device__ float g_mu[HDIM];
__device__ float g_var[HDIM];
__device__ float g_wpe[ODIM*HDIM];
__device__ float g_be[ODIM];

// gate prescale constants: r,z rows by -log2e; n rows by -2*log2e
#define C_RZ (-1.4426950408889634f)
#define C_N  (-2.8853900817779268f)

// ---------------- f32x2 helpers (FFMA2 path, sm_103a) ----------------
__device__ __forceinline__ unsigned long long pk2(float x, float y) {
    unsigned long long r;
    asm("mov.b64 %0, {%1,%2};" : "=l"(r) : "f"(x), "f"(y));
    return r;
}
__device__ __forceinline__ void upk2(unsigned long long v, float &x, float &y) {
    asm("mov.b64 {%0,%1}, %2;" : "=f"(x), "=f"(y) : "l"(v));
}
__device__ __forceinline__ unsigned long long ffma2(unsigned long long a,
                                                    unsigned long long b,
                                                    unsigned long long c) {
    unsigned long long d;
    asm("fma.rn.f32x2 %0, %1, %2, %3;" : "=l"(d) : "l"(a), "l"(b), "l"(c));
    return d;
}
__device__ __forceinline__ unsigned long long fadd2(unsigned long long a,
                                                    unsigned long long b) {
    unsigned long long d;
    asm("add.rn.f32x2 %0, %1, %2;" : "=l"(d) : "l"(a), "l"(b));
    return d;
}
__device__ __forceinline__ float hsum2(unsigned long long v) {
    float x, y; upk2(v, x, y); return x + y;
}
__device__ __forceinline__ float ex2a(float x) {
    float y; asm("ex2.approx.f32 %0, %1;" : "=f"(y) : "f"(x)); return y;
}
__device__ __forceinline__ float rcpa(float x) {
    float y; asm("rcp.approx.f32 %0, %1;" : "=f"(y) : "f"(x)); return y;
}

// general-purpose (non-GRU) activations
__device__ __forceinline__ float sigm(float x) {
    return __fdividef(1.0f, 1.0f + __expf(-x));
}

// ---------------- stage 1: xp = seq @ Wih.T + bih (both GRUs), PRE-SCALED ----
// seq[s][f] = x_seq[b, 7, f, jn], s = b*2048 + jn
// Output rows j<128 (r,z gates) are scaled by C_RZ; rows j>=128 (n) by C_N,
// so the GRU computes gates directly in the exp2 domain.
__global__ void __launch_bounds__(384) xp_kernel(const float* __restrict__ x,
                                                 const float* __restrict__ WihS,
                                                 const float* __restrict__ bihS,
                                                 const float* __restrict__ Wih,
                                                 const float* __restrict__ bih) {
    __shared__ float sq[16][64];
    const int tid = threadIdx.x;
    const int base = blockIdx.x * 16;
    for (int t = tid; t < 16 * 64; t += 384) {
        int f = t >> 4, r = t & 15;
        int s = base + r;
        int b = s >> 11, jn = s & 2047;
        sq[r][f] = x[((b * 8 + 7) * 64 + f) * 2048 + jn];
    }
    __syncthreads();
    const int which = (tid >= G3H) ? 1 : 0;
    const int j = which ? tid - G3H : tid;
    const float* W = which ? Wih : WihS;
    const float bz = which ? bih[j] : bihS[j];
    const float scale = (j < 128) ? C_RZ : C_N;
    float wr[64];
#pragma unroll
    for (int f = 0; f < 64; f++) wr[f] = W[j * 64 + f];
    for (int r = 0; r < 16; r++) {
        float acc = bz;
#pragma unroll
        for (int f = 0; f < 64; f++) acc = fmaf(sq[r][f], wr[f], acc);
        g_xp[which][base + r][j] = acc * scale;
    }
}

// ---------------- stage 2: sequential GRU scans (2 blocks, one per GRU) ----------------
// 128 threads: thread (j, half) computes r/z/n partial dots over 32 h elems
// with pre-scaled weights; halves merged by ONE shfl_xor; gates are pure
// ex2.approx + rcp.approx chains (no div, no mul-by-log2e, no copysign).
__global__ void __launch_bounds__(128, 1) gru_kernel(const float* __restrict__ Whh0,
                                                     const float* __restrict__ bhh0,
                                                     const float* __restrict__ Whh1,
                                                     const float* __restrict__ bhh1) {
    const int g = blockIdx.x;
    const float* Whh = g ? Whh1 : Whh0;
    const float* bhh = g ? bhh1 : bhh0;
    const float* xp = &g_xp[g][0][0];
    float* hout = &g_h[g][0][0];

    const int tid = threadIdx.x;
    const int j = tid >> 1;      // 0..63
    const int half = tid & 1;    // which 32-element half of h
    const int hoff = half * 32;

    // weight rows for gates r,z,n (this thread's half), packed f32x2, PRE-SCALED
    unsigned long long wr[16], wz[16], wn[16];
    {
        const float2* pr = (const float2*)(Whh + (size_t)j * 64 + hoff);
        const float2* pz = (const float2*)(Whh + (size_t)(64 + j) * 64 + hoff);
        const float2* pn = (const float2*)(Whh + (size_t)(128 + j) * 64 + hoff);
#pragma unroll
        for (int k = 0; k < 16; k++) {
            float2 a = pr[k]; wr[k] = pk2(a.x * C_RZ, a.y * C_RZ);
            float2 b = pz[k]; wz[k] = pk2(b.x * C_RZ, b.y * C_RZ);
            float2 c = pn[k]; wn[k] = pk2(c.x * C_N,  c.y * C_N);
        }
    }
    const float br  = bhh[j] * C_RZ;
    const float bz2 = bhh[64 + j] * C_RZ;
    const float bn  = bhh[128 + j] * C_N;

    __shared__ __align__(16) float shh[2][64];
    if (tid < 64) shh[0][tid] = 0.0f;

    // 2-deep xp prefetch pipeline (rows are pre-scaled)
    float xr0 = xp[j],        xz0 = xp[64 + j],        xn0 = xp[128 + j];
    float xr1 = xp[G3H + j],  xz1 = xp[G3H + 64 + j],  xn1 = xp[G3H + 128 + j];
    __syncthreads();

    int p = 0;
    const unsigned FULL = 0xffffffffu;
#pragma unroll 2
    for (int s = 0; s < NSEQ; s++) {
        // prefetch xt for s+2 (xp padded: no bounds check)
        const float* pq = xp + (size_t)(s + 2) * G3H;
        float xr2 = __ldg(pq + j);
        float xz2 = __ldg(pq + 64 + j);
        float xn2 = __ldg(pq + 128 + j);

        float hj = shh[p][j];
        const ulonglong2* hp2 = (const ulonglong2*)(&shh[p][hoff]);
        unsigned long long ar0 = 0ull, ar1 = 0ull;
        unsigned long long az0 = 0ull, az1 = 0ull;
        unsigned long long an0 = 0ull, an1 = 0ull;
#pragma unroll
        for (int k = 0; k < 8; k++) {
            ulonglong2 h2 = hp2[k];
            ar0 = ffma2(wr[2 * k],     h2.x, ar0);
            ar1 = ffma2(wr[2 * k + 1], h2.y, ar1);
            az0 = ffma2(wz[2 * k],     h2.x, az0);
            az1 = ffma2(wz[2 * k + 1], h2.y, az1);
            an0 = ffma2(wn[2 * k],     h2.x, an0);
            an1 = ffma2(wn[2 * k + 1], h2.y, an1);
        }
        float sr = hsum2(fadd2(ar0, ar1));
        float sz = hsum2(fadd2(az0, az1));
        float sn = hsum2(fadd2(an0, an1));
        sr += __shfl_xor_sync(FULL, sr, 1);
        sz += __shfl_xor_sync(FULL, sz, 1);
        sn += __shfl_xor_sync(FULL, sn, 1);

        // gates in exp2 domain:
        // r = sigmoid(u) = 1/(1+2^(C_RZ*u)); pre-activation already scaled.
        float r = rcpa(1.0f + ex2a(xr0 + br + sr));
        float z = rcpa(1.0f + ex2a(xz0 + bz2 + sz));
        // ng = tanh(t) = 2/(1+2^(C_N*t)) - 1; tp = C_N*t assembled from scaled parts
        float tp = fmaf(r, bn + sn, xn0);
        float ng = fmaf(2.0f, rcpa(1.0f + ex2a(tp)), -1.0f);
        float hn = fmaf(z, hj - ng, ng);   // (1-z)*ng + z*h

        int np = p ^ 1;
        if (half == 0) {
            shh[np][j] = hn;
            hout[(size_t)s * 64 + j] = hn;
        }
        xr0 = xr1; xz0 = xz1; xn0 = xn1;
        xr1 = xr2; xz1 = xz2; xn1 = xn2;
        p = np;
        __syncthreads();
    }
}

// ---------------- stage 3: sim[b] = H H^T (per batch), 64x64 tiles ----------------
__global__ void __launch_bounds__(256) sim_kernel() {
    const int b = blockIdx.z, bi = blockIdx.y, bj = blockIdx.x;
    __shared__ float A[64][65];
    __shared__ float B[64][65];
    const int tid = threadIdx.x;
    const float* H = &g_h[0][(size_t)b * NNODE][0];
    for (int t = tid; t < 4096; t += 256) {
        int r = t >> 6, c = t & 63;
        A[r][c] = H[(bi * 64 + r) * 64 + c];
        B[r][c] = H[(bj * 64 + r) * 64 + c];
    }
    __syncthreads();
    const int ty = tid >> 4, tx = tid & 15;
    float acc[4][4];
#pragma unroll
    for (int u = 0; u < 4; u++)
#pragma unroll
        for (int v = 0; v < 4; v++) acc[u][v] = 0.f;
    for (int k = 0; k < 64; k++) {
        float a[4], bb[4];
#pragma unroll
        for (int u = 0; u < 4; u++) a[u] = A[ty * 4 + u][k];
#pragma unroll
        for (int v = 0; v < 4; v++) bb[v] = B[tx * 4 + v][k];
#pragma unroll
        for (int u = 0; u < 4; u++)
#pragma unroll
            for (int v = 0; v < 4; v++) acc[u][v] = fmaf(a[u], bb[v], acc[u][v]);
    }
    float* C = &g_sim[b][0];
#pragma unroll
    for (int u = 0; u < 4; u++)
#pragma unroll
        for (int v = 0; v < 4; v++)
            C[(size_t)(bi * 64 + ty * 4 + u) * NNODE + (bj * 64 + tx * 4 + v)] = acc[u][v];
}

// ---------------- stage 4: per-row top-8 (one warp per row, float4 stream) ----------------
__device__ __forceinline__ void tk_insert(float v, int jj, float* v8, int* i8) {
    if (v > v8[7]) {
        v8[7] = v; i8[7] = jj;
#pragma unroll
        for (int q = 7; q > 0; q--) {
            if (v8[q] > v8[q - 1]) {
                float tv = v8[q - 1]; v8[q - 1] = v8[q]; v8[q] = tv;
                int ti = i8[q - 1]; i8[q - 1] = i8[q]; i8[q] = ti;
            }
        }
    }
}

__global__ void __launch_bounds__(128) topk_kernel() {
    const int warp = threadIdx.x >> 5, lane = threadIdx.x & 31;
    const int row = blockIdx.x * 4 + warp;  // 0..8191
    const int b = row >> 11, i = row & 2047;
    const float4* S4 = (const float4*)&g_sim[b][(size_t)i * NNODE];

    float v8[8]; int i8[8];
#pragma unroll
    for (int t = 0; t < 8; t++) { v8[t] = -3.402823e38f; i8[t] = -1; }

#pragma unroll 2
    for (int q = lane; q < NNODE / 4; q += 32) {
        float4 v = S4[q];
        int jj = q * 4;
        if (jj != i)     tk_insert(v.x, jj,     v8, i8);
        if (jj + 1 != i) tk_insert(v.y, jj + 1, v8, i8);
        if (jj + 2 != i) tk_insert(v.z, jj + 2, v8, i8);
        if (jj + 3 != i) tk_insert(v.w, jj + 3, v8, i8);
    }

    // warp merge: 8 rounds of argmax over each lane's current head
    const unsigned FULL = 0xffffffffu;
    for (int t = 0; t < KNN; t++) {
        float bv = v8[0]; int bi2 = i8[0]; int bl = lane;
#pragma unroll
        for (int off = 16; off > 0; off >>= 1) {
            float ov = __shfl_down_sync(FULL, bv, off);
            int oi = __shfl_down_sync(FULL, bi2, off);
            int ol = __shfl_down_sync(FULL, bl, off);
            if (ov > bv || (ov == bv && oi < bi2)) { bv = ov; bi2 = oi; bl = ol; }
        }
        bv = __shfl_sync(FULL, bv, 0);
        bi2 = __shfl_sync(FULL, bi2, 0);
        bl = __shfl_sync(FULL, bl, 0);
        if (lane == bl) {
#pragma unroll
            for (int q = 0; q < 7; q++) { v8[q] = v8[q + 1]; i8[q] = i8[q + 1]; }
            v8[7] = -3.402823e38f; i8[7] = -1;
        }
        if (lane == 0) { g_vals[row][t] = bv; g_idx[row][t] = bi2; }
    }
}

// ---------------- stage 5: degree + dinv ----------------
__global__ void deg_init_kernel() {
    int t = blockIdx.x * 256 + threadIdx.x;
    if (t < NSEQ) g_deg[t] = 1.0f;  // self loop weight
}
__global__ void deg_scatter_kernel() {
    int t = blockIdx.x * 256 + threadIdx.x;
    if (t < NSEQ * KNN) {
        int s = t >> 3, k = t & 7;
        int b = s >> 11;
        atomicAdd(&g_deg[(b << 11) + g_idx[s][k]], g_vals[s][k]);
    }
}
__global__ void dinv_kernel() {
    int t = blockIdx.x * 256 + threadIdx.x;
    if (t < NSEQ) {
        float di = rsqrtf(g_deg[t]);
        if (isinf(di)) di = 0.0f;
        g_dinv[t] = di;
    }
}

// ---------------- stage 6: xw = act(X) @ W.T ----------------
__global__ void __launch_bounds__(256) xw_kernel(const float* __restrict__ W,
                                                 int src, int relu) {
    __shared__ float sx[4][64];
    __shared__ float wT[64][64];
    const int tid = threadIdx.x;
    const float* X = src ? g_o1 : &g_h[1][0][0];
    for (int t = tid; t < 4096; t += 256) {
        int jj = t >> 6, f = t & 63;
        wT[f][jj] = W[jj * 64 + f];
    }
    const int s0 = blockIdx.x * 4;
    {
        int r = tid >> 6, f = tid & 63;
        float v = X[(s0 + r) * 64 + f];
        if (relu) v = fmaxf(v, 0.0f);
        sx[r][f] = v;
    }
    __syncthreads();
    const int r = tid >> 6, j = tid & 63;
    float acc = 0.f;
#pragma unroll
    for (int f = 0; f < 64; f++) acc = fmaf(sx[r][f], wT[f][j], acc);
    g_xw[(s0 + r) * 64 + j] = acc;
}

// ---------------- stage 7: GCN init (bias + self loop) + scatter ----------------
__global__ void init_out_kernel(int layer, const float* __restrict__ bias) {
    int t = blockIdx.x * 256 + threadIdx.x;  // < 524288
    int s = t >> 6, j = t & 63;
    float di = g_dinv[s];
    float* O = layer ? g_o2 : g_o1;
    O[t] = bias[j] + di * di * g_xw[t];
}
__global__ void scatter_kernel(int layer) {
    int t = blockIdx.x * 256 + threadIdx.x;  // < 4194304
    int e = t >> 6, c = t & 63;
    int s = e >> 3, k = e & 7;
    int b = s >> 11;
    int dst = (b << 11) + g_idx[s][k];
    float norm = g_dinv[s] * g_vals[s][k] * g_dinv[dst];
    float* O = layer ? g_o2 : g_o1;
    atomicAdd(&O[dst * 64 + c], norm * g_xw[s * 64 + c]);
}

// ---------------- stage 8: BN stats over relu(o2) ----------------
__global__ void __launch_bounds__(256) stats_kernel() {
    const int c = blockIdx.x;
    float s = 0.f, q = 0.f;
    for (int r = threadIdx.x; r < NSEQ; r += 256) {
        float v = fmaxf(g_o2[r * 64 + c], 0.0f);
        s += v;
        q = fmaf(v, v, q);
    }
    __shared__ float ss[256], sq2[256];
    ss[threadIdx.x] = s; sq2[threadIdx.x] = q;
    __syncthreads();
    for (int o = 128; o > 0; o >>= 1) {
        if (threadIdx.x < o) {
            ss[threadIdx.x] += ss[threadIdx.x + o];
            sq2[threadIdx.x] += sq2[threadIdx.x + o];
        }
        __syncthreads();
    }
    if (threadIdx.x == 0) {
        float mu = ss[0] / (float)NSEQ;
        g_mu[c] = mu;
        g_var[c] = sq2[0] / (float)NSEQ - mu * mu;
    }
}

// ---------------- stage 9: fold BN into predictor ----------------
__global__ void __launch_bounds__(64) prep_kernel(const float* __restrict__ gamma,
                                                  const float* __restrict__ beta,
                                                  const float* __restrict__ Wp,
                                                  const float* __restrict__ bp) {
    __shared__ float sa[64], sm[64];
    const int c = threadIdx.x;
    float a = gamma[c] * rsqrtf(g_var[c] + 1e-5f);
    sa[c] = a;
    sm[c] = beta[c] - g_mu[c] * a;
    __syncthreads();
    for (int t = c; t < ODIM * 64; t += 64) {
        int o = t >> 6, cc = t & 63;
        g_wpe[o * 64 + cc] = Wp[o * 64 + cc] * sa[cc];
    }
    if (c < ODIM) {
        float acc = bp[c];
#pragma unroll
        for (int cc = 0; cc < 64; cc++) acc = fmaf(sm[cc], Wp[c * 64 + cc], acc);
        g_be[c] = acc;
    }
}

// ---------------- stage 10: out = relu(o2) @ Wp'.T + b' ----------------
__global__ void __launch_bounds__(256) final_kernel(float* __restrict__ out) {
    __shared__ float sx[8][64];
    __shared__ float wT[64][32];
    __shared__ float sb[32];
    const int tid = threadIdx.x;
    const int s0 = blockIdx.x * 8;
    for (int t = tid; t < ODIM * 64; t += 256) {
        int o = t >> 6, cc = t & 63;
        wT[cc][o] = g_wpe[o * 64 + cc];
    }
    for (int t = tid; t < 512; t += 256) {
        int r = t >> 6, cc = t & 63;
        sx[r][cc] = fmaxf(g_o2[(s0 + r) * 64 + cc], 0.0f);
    }
    if (tid < ODIM) sb[tid] = g_be[tid];
    __syncthreads();
    const int r = tid >> 5, o = tid & 31;
    float acc = sb[o];
#pragma unroll
    for (int cc = 0; cc < 64; cc++) acc = fmaf(sx[r][cc], wT[cc][o], acc);
    out[(s0 + r) * ODIM + o] = acc;
}

// ---------------- launch ----------------
extern "C" void kernel_launch(void* const* d_in, const int* in_sizes, int n_in,
                              void* d_out, int out_size) {
    const float* x     = (const float*)d_in[0];   // [4,8,64,2048]
    const float* WihS  = (const float*)d_in[1];
    const float* WhhS  = (const float*)d_in[2];
    const float* bihS  = (const float*)d_in[3];
    const float* bhhS  = (const float*)d_in[4];
    const float* Wih   = (const float*)d_in[5];
    const float* Whh   = (const float*)d_in[6];
    const float* bih   = (const float*)d_in[7];
    const float* bhh   = (const float*)d_in[8];
    const float* W1    = (const float*)d_in[9];
    const float* b1    = (const float*)d_in[10];
    const float* W2    = (const float*)d_in[11];
    const float* b2    = (const float*)d_in[12];
    const float* gamma = (const float*)d_in[13];
    const float* beta  = (const float*)d_in[14];
    const float* Wp    = (const float*)d_in[15];
    const float* bp    = (const float*)d_in[16];
    float* out = (float*)d_out;

    xp_kernel<<<NSEQ / 16, 384>>>(x, WihS, bihS, Wih, bih);
    gru_kernel<<<2, 128>>>(WhhS, bhhS, Whh, bhh);
    sim_kernel<<<dim3(32, 32, 4), 256>>>();
    topk_kernel<<<NSEQ / 4, 128>>>();
    deg_init_kernel<<<NSEQ / 256, 256>>>();
    deg_scatter_kernel<<<NSEQ * KNN / 256, 256>>>();
    dinv_kernel<<<NSEQ / 256, 256>>>();

    // GCN layer 1: input h_out (no relu)
    xw_kernel<<<NSEQ / 4, 256>>>(W1, 0, 0);
    init_out_kernel<<<NSEQ * 64 / 256, 256>>>(0, b1);
    scatter_kernel<<<NSEQ * KNN * 64 / 256, 256>>>(0);

    // GCN layer 2: input relu(o1)
    xw_kernel<<<NSEQ / 4, 256>>>(W2, 1, 1);
    init_out_kernel<<<NSEQ * 64 / 256, 256>>>(1, b2);
    scatter_kernel<<<NSEQ * KNN * 64 / 256, 256>>>(1);

    // BN + predictor
    stats_kernel<<<64, 256>>>();
    prep_kernel<<<1, 64>>>(gamma, beta, Wp, bp);
    final_kernel<<<NSEQ / 8, 256>>>(out);
}